// round 1
// baseline (speedup 1.0000x reference)
#include <cuda_runtime.h>
#include <math.h>

#define BATCH 4
#define SEQ 2048
#define M_ROWS 8192          // BATCH*SEQ
#define D_MODEL 1024
#define NH 16
#define DK 64
#define D_FF 4096

// ---------------- scratch (device globals; no allocation allowed) ----------------
__device__ float g_xn[M_ROWS * D_MODEL];    // layernorm output
__device__ float g_q[M_ROWS * D_MODEL];     // (b,h,s,d)
__device__ float g_k[M_ROWS * D_MODEL];     // (b,h,s,d)
__device__ float g_v[M_ROWS * D_MODEL];     // (b,h,s,d)
__device__ float g_attn[M_ROWS * D_MODEL];  // (b,s,h*dk) row-major
__device__ float g_x1[M_ROWS * D_MODEL];    // residual after attention
__device__ float g_h[M_ROWS * D_FF];        // FFN hidden

// ---------------- block reduction helper ----------------
__device__ __forceinline__ float block_sum_256(float v, float* red) {
    int t = threadIdx.x;
    #pragma unroll
    for (int o = 16; o; o >>= 1) v += __shfl_xor_sync(0xffffffffu, v, o);
    if ((t & 31) == 0) red[t >> 5] = v;
    __syncthreads();
    if (t < 32) {
        float r = (t < 8) ? red[t] : 0.f;
        #pragma unroll
        for (int o = 4; o; o >>= 1) r += __shfl_xor_sync(0xffffffffu, r, o);
        if (t == 0) red[0] = r;
    }
    __syncthreads();
    float out = red[0];
    __syncthreads();
    return out;
}

// ---------------- LayerNorm: one block per row, 256 threads ----------------
__global__ void ln_kernel(const float* __restrict__ x, const float* __restrict__ gamma,
                          const float* __restrict__ beta, float* __restrict__ out) {
    __shared__ float red[8];
    int row = blockIdx.x;
    int t = threadIdx.x;
    const float4* xr = (const float4*)(x + (size_t)row * D_MODEL);
    float4 v = xr[t];
    float mean = block_sum_256(v.x + v.y + v.z + v.w, red) * (1.0f / D_MODEL);
    float dx = v.x - mean, dy = v.y - mean, dz = v.z - mean, dw = v.w - mean;
    float var = block_sum_256(dx * dx + dy * dy + dz * dz + dw * dw, red) * (1.0f / D_MODEL);
    float rstd = rsqrtf(var + 1e-6f);
    float4 ga = ((const float4*)gamma)[t];
    float4 bb = ((const float4*)beta)[t];
    float4 o;
    o.x = ga.x * dx * rstd + bb.x;
    o.y = ga.y * dy * rstd + bb.y;
    o.z = ga.z * dz * rstd + bb.z;
    o.w = ga.w * dw * rstd + bb.w;
    ((float4*)(out + (size_t)row * D_MODEL))[t] = o;
}

// ---------------- GEMM: C[M,N] = A[M,K] * W[N,K]^T  (both K-contiguous) -----------
// 128x128 block tile, BK=16, 256 threads, 8x8 per-thread register tile.
// MODE 0: scatter to (b,h,s,d) q/k/v layout
// MODE 1: C = res + A*W^T (+ bias if non-null)
// MODE 2: C = relu(A*W^T + bias)
template <int MODE>
__global__ __launch_bounds__(256) void gemm_nt(
    const float* __restrict__ A, const float* __restrict__ W,
    const float* __restrict__ bias, const float* __restrict__ res,
    float* __restrict__ C, int N, int K) {
    __shared__ float As[16][132];
    __shared__ float Bs[16][132];
    int tid = threadIdx.x;
    int bm = blockIdx.y * 128;
    int bn = blockIdx.x * 128;
    int tm = tid >> 4, tn = tid & 15;
    float acc[8][8] = {};
    const float* Ab = A + (size_t)bm * K;
    const float* Wb = W + (size_t)bn * K;
    int r0 = tid >> 2;           // 0..63
    int c0 = (tid & 3) * 4;      // 0,4,8,12
    for (int k0 = 0; k0 < K; k0 += 16) {
        #pragma unroll
        for (int it = 0; it < 2; it++) {
            int r = r0 + it * 64;
            float4 av = *(const float4*)(Ab + (size_t)r * K + k0 + c0);
            As[c0 + 0][r] = av.x; As[c0 + 1][r] = av.y;
            As[c0 + 2][r] = av.z; As[c0 + 3][r] = av.w;
            float4 wv = *(const float4*)(Wb + (size_t)r * K + k0 + c0);
            Bs[c0 + 0][r] = wv.x; Bs[c0 + 1][r] = wv.y;
            Bs[c0 + 2][r] = wv.z; Bs[c0 + 3][r] = wv.w;
        }
        __syncthreads();
        #pragma unroll
        for (int k = 0; k < 16; k++) {
            float4 a0 = *(const float4*)&As[k][tm * 8];
            float4 a1 = *(const float4*)&As[k][tm * 8 + 4];
            float4 b0 = *(const float4*)&Bs[k][tn * 8];
            float4 b1 = *(const float4*)&Bs[k][tn * 8 + 4];
            float a[8] = {a0.x, a0.y, a0.z, a0.w, a1.x, a1.y, a1.z, a1.w};
            float b[8] = {b0.x, b0.y, b0.z, b0.w, b1.x, b1.y, b1.z, b1.w};
            #pragma unroll
            for (int i = 0; i < 8; i++)
                #pragma unroll
                for (int j = 0; j < 8; j++) acc[i][j] = fmaf(a[i], b[j], acc[i][j]);
        }
        __syncthreads();
    }
    #pragma unroll
    for (int i = 0; i < 8; i++) {
        int m = bm + tm * 8 + i;
        #pragma unroll
        for (int j = 0; j < 8; j++) {
            int n = bn + tn * 8 + j;
            float c = acc[i][j];
            if (MODE == 0) {
                int b = m >> 11, s = m & 2047, h = n >> 6, d = n & 63;
                C[(((size_t)(b * NH + h) * SEQ + s) << 6) + d] = c;
            } else if (MODE == 1) {
                if (bias) c += bias[n];
                C[(size_t)m * N + n] = res[(size_t)m * N + n] + c;
            } else {
                c += bias[n];
                C[(size_t)m * N + n] = fmaxf(c, 0.0f);
            }
        }
    }
}

// ---------------- Flash attention, fp32, 64q x 64k tiles ----------------
// grid: (B*H, SEQ/64), 256 threads (16x16), dynamic smem.
__global__ __launch_bounds__(256) void attn_kernel(
    const float* __restrict__ q, const float* __restrict__ k,
    const float* __restrict__ v, const int* __restrict__ mask,
    float* __restrict__ out) {
    extern __shared__ float sm[];
    float* Qs = sm;                 // 64*64
    float* Ks = Qs + 64 * 64;       // 64*65
    float* Vs = Ks + 64 * 65;       // 64*65
    float* Ps = Vs + 64 * 65;       // 64*64
    float* row_m = Ps + 64 * 64;    // 64
    float* row_l = row_m + 64;      // 64
    float* row_sc = row_l + 64;     // 64
    int* Msk = (int*)(row_sc + 64); // 64

    int bh = blockIdx.x;    // b*NH + h
    int qt = blockIdx.y;    // query tile
    int b = bh >> 4;
    int h = bh & 15;
    int tid = threadIdx.x;
    int qy = tid >> 4, kx = tid & 15;

    const float* qbase = q + ((size_t)bh * SEQ + qt * 64) * DK;
    const float* kbase = k + (size_t)bh * SEQ * DK;
    const float* vbase = v + (size_t)bh * SEQ * DK;
    const int* mbase = mask + b * SEQ;

    // load Q tile
    for (int i = tid; i < 1024; i += 256) {
        int r = i >> 4, c = (i & 15) * 4;
        float4 t4 = *(const float4*)(qbase + (size_t)r * DK + c);
        Qs[r * 64 + c] = t4.x; Qs[r * 64 + c + 1] = t4.y;
        Qs[r * 64 + c + 2] = t4.z; Qs[r * 64 + c + 3] = t4.w;
    }
    if (tid < 64) { row_m[tid] = -1e30f; row_l[tid] = 0.f; }
    __syncthreads();

    float acc[4][4] = {};
    const float scale = 0.125f;   // 1/sqrt(64)

    for (int kt = 0; kt < SEQ; kt += 64) {
        // load K & V tiles, mask slice
        for (int i = tid; i < 1024; i += 256) {
            int r = i >> 4, c = (i & 15) * 4;
            float4 t4 = *(const float4*)(kbase + (size_t)(kt + r) * DK + c);
            Ks[r * 65 + c] = t4.x; Ks[r * 65 + c + 1] = t4.y;
            Ks[r * 65 + c + 2] = t4.z; Ks[r * 65 + c + 3] = t4.w;
            float4 u4 = *(const float4*)(vbase + (size_t)(kt + r) * DK + c);
            Vs[r * 65 + c] = u4.x; Vs[r * 65 + c + 1] = u4.y;
            Vs[r * 65 + c + 2] = u4.z; Vs[r * 65 + c + 3] = u4.w;
        }
        if (tid < 64) Msk[tid] = mbase[kt + tid];
        __syncthreads();

        // scores: 4x4 register tile over (q rows, k cols)
        float s4[4][4] = {};
        const float* q0 = &Qs[(qy * 4 + 0) * 64];
        const float* q1 = &Qs[(qy * 4 + 1) * 64];
        const float* q2 = &Qs[(qy * 4 + 2) * 64];
        const float* q3 = &Qs[(qy * 4 + 3) * 64];
        const float* k0 = &Ks[(kx * 4 + 0) * 65];
        const float* k1 = &Ks[(kx * 4 + 1) * 65];
        const float* k2 = &Ks[(kx * 4 + 2) * 65];
        const float* k3 = &Ks[(kx * 4 + 3) * 65];
        #pragma unroll 16
        for (int d = 0; d < 64; d++) {
            float a0 = q0[d], a1 = q1[d], a2 = q2[d], a3 = q3[d];
            float b0 = k0[d], b1 = k1[d], b2 = k2[d], b3 = k3[d];
            s4[0][0] = fmaf(a0, b0, s4[0][0]); s4[0][1] = fmaf(a0, b1, s4[0][1]);
            s4[0][2] = fmaf(a0, b2, s4[0][2]); s4[0][3] = fmaf(a0, b3, s4[0][3]);
            s4[1][0] = fmaf(a1, b0, s4[1][0]); s4[1][1] = fmaf(a1, b1, s4[1][1]);
            s4[1][2] = fmaf(a1, b2, s4[1][2]); s4[1][3] = fmaf(a1, b3, s4[1][3]);
            s4[2][0] = fmaf(a2, b0, s4[2][0]); s4[2][1] = fmaf(a2, b1, s4[2][1]);
            s4[2][2] = fmaf(a2, b2, s4[2][2]); s4[2][3] = fmaf(a2, b3, s4[2][3]);
            s4[3][0] = fmaf(a3, b0, s4[3][0]); s4[3][1] = fmaf(a3, b1, s4[3][1]);
            s4[3][2] = fmaf(a3, b2, s4[3][2]); s4[3][3] = fmaf(a3, b3, s4[3][3]);
        }
        // scale + mask, tile row max
        float tmax[4];
        #pragma unroll
        for (int i = 0; i < 4; i++) {
            tmax[i] = -1e30f;
            #pragma unroll
            for (int j = 0; j < 4; j++) {
                float sv = s4[i][j] * scale;
                if (Msk[kx * 4 + j] == 0) sv = -1e30f;
                s4[i][j] = sv;
                tmax[i] = fmaxf(tmax[i], sv);
            }
            #pragma unroll
            for (int o = 8; o; o >>= 1)
                tmax[i] = fmaxf(tmax[i], __shfl_xor_sync(0xffffffffu, tmax[i], o));
        }
        if (kx == 0) {
            #pragma unroll
            for (int i = 0; i < 4; i++) {
                int qr = qy * 4 + i;
                float mold = row_m[qr];
                float mnew = fmaxf(mold, tmax[i]);
                row_sc[qr] = __expf(mold - mnew);
                row_m[qr] = mnew;
            }
        }
        __syncthreads();
        // probabilities + row sums + rescale accumulators
        #pragma unroll
        for (int i = 0; i < 4; i++) {
            int qr = qy * 4 + i;
            float mn = row_m[qr];
            float lsum = 0.f;
            #pragma unroll
            for (int j = 0; j < 4; j++) {
                float p = __expf(s4[i][j] - mn);
                Ps[qr * 64 + kx * 4 + j] = p;
                lsum += p;
            }
            #pragma unroll
            for (int o = 8; o; o >>= 1) lsum += __shfl_xor_sync(0xffffffffu, lsum, o);
            if (kx == 0) row_l[qr] = row_l[qr] * row_sc[qr] + lsum;
            float sc = row_sc[qr];
            #pragma unroll
            for (int j = 0; j < 4; j++) acc[i][j] *= sc;
        }
        __syncthreads();
        // O += P @ V
        const float* p0 = &Ps[(qy * 4 + 0) * 64];
        const float* p1 = &Ps[(qy * 4 + 1) * 64];
        const float* p2 = &Ps[(qy * 4 + 2) * 64];
        const float* p3 = &Ps[(qy * 4 + 3) * 64];
        #pragma unroll 8
        for (int kk = 0; kk < 64; kk++) {
            float b0 = Vs[kk * 65 + kx * 4 + 0];
            float b1 = Vs[kk * 65 + kx * 4 + 1];
            float b2 = Vs[kk * 65 + kx * 4 + 2];
            float b3 = Vs[kk * 65 + kx * 4 + 3];
            float a0 = p0[kk], a1 = p1[kk], a2 = p2[kk], a3 = p3[kk];
            acc[0][0] = fmaf(a0, b0, acc[0][0]); acc[0][1] = fmaf(a0, b1, acc[0][1]);
            acc[0][2] = fmaf(a0, b2, acc[0][2]); acc[0][3] = fmaf(a0, b3, acc[0][3]);
            acc[1][0] = fmaf(a1, b0, acc[1][0]); acc[1][1] = fmaf(a1, b1, acc[1][1]);
            acc[1][2] = fmaf(a1, b2, acc[1][2]); acc[1][3] = fmaf(a1, b3, acc[1][3]);
            acc[2][0] = fmaf(a2, b0, acc[2][0]); acc[2][1] = fmaf(a2, b1, acc[2][1]);
            acc[2][2] = fmaf(a2, b2, acc[2][2]); acc[2][3] = fmaf(a2, b3, acc[2][3]);
            acc[3][0] = fmaf(a3, b0, acc[3][0]); acc[3][1] = fmaf(a3, b1, acc[3][1]);
            acc[3][2] = fmaf(a3, b2, acc[3][2]); acc[3][3] = fmaf(a3, b3, acc[3][3]);
        }
        __syncthreads();
    }
    // finalize: divide by l, write (b, s, h*DK + d)
    #pragma unroll
    for (int i = 0; i < 4; i++) {
        int qr = qy * 4 + i;
        float inv = 1.0f / row_l[qr];
        int srow = qt * 64 + qr;
        float* op = out + ((size_t)b * SEQ + srow) * D_MODEL + h * DK + kx * 4;
        #pragma unroll
        for (int j = 0; j < 4; j++) op[j] = acc[i][j] * inv;
    }
}

// ---------------- launch ----------------
extern "C" void kernel_launch(void* const* d_in, const int* in_sizes, int n_in,
                              void* d_out, int out_size) {
    const float* x      = (const float*)d_in[0];
    const int*   mask   = (const int*)d_in[1];
    const float* wq     = (const float*)d_in[2];
    const float* wk     = (const float*)d_in[3];
    const float* wv     = (const float*)d_in[4];
    const float* wo     = (const float*)d_in[5];
    const float* ln1_a  = (const float*)d_in[6];
    const float* ln1_b  = (const float*)d_in[7];
    const float* ln2_a  = (const float*)d_in[8];
    const float* ln2_b  = (const float*)d_in[9];
    const float* w1     = (const float*)d_in[10];
    const float* b1     = (const float*)d_in[11];
    const float* w2     = (const float*)d_in[12];
    const float* b2     = (const float*)d_in[13];
    float* out = (float*)d_out;

    float *xn, *q, *k, *v, *attn, *x1, *hbuf;
    cudaGetSymbolAddress((void**)&xn, g_xn);
    cudaGetSymbolAddress((void**)&q, g_q);
    cudaGetSymbolAddress((void**)&k, g_k);
    cudaGetSymbolAddress((void**)&v, g_v);
    cudaGetSymbolAddress((void**)&attn, g_attn);
    cudaGetSymbolAddress((void**)&x1, g_x1);
    cudaGetSymbolAddress((void**)&hbuf, g_h);

    // LN1
    ln_kernel<<<M_ROWS, 256>>>(x, ln1_a, ln1_b, xn);
    // QKV projections (scatter to b,h,s,d)
    dim3 g1024(D_MODEL / 128, M_ROWS / 128);
    gemm_nt<0><<<g1024, 256>>>(xn, wq, nullptr, nullptr, q, D_MODEL, D_MODEL);
    gemm_nt<0><<<g1024, 256>>>(xn, wk, nullptr, nullptr, k, D_MODEL, D_MODEL);
    gemm_nt<0><<<g1024, 256>>>(xn, wv, nullptr, nullptr, v, D_MODEL, D_MODEL);
    // attention
    size_t smem = (size_t)(64 * 64 + 64 * 65 + 64 * 65 + 64 * 64 + 4 * 64) * sizeof(float);
    cudaFuncSetAttribute(attn_kernel, cudaFuncAttributeMaxDynamicSharedMemorySize, (int)smem);
    attn_kernel<<<dim3(BATCH * NH, SEQ / 64), 256, smem>>>(q, k, v, mask, attn);
    // O-projection + residual: x1 = x + attn @ wo^T
    gemm_nt<1><<<g1024, 256>>>(attn, wo, nullptr, x, x1, D_MODEL, D_MODEL);
    // LN2
    ln_kernel<<<M_ROWS, 256>>>(x1, ln2_a, ln2_b, xn);
    // FFN1: h = relu(xn @ w1^T + b1)
    dim3 gff(D_FF / 128, M_ROWS / 128);
    gemm_nt<2><<<gff, 256>>>(xn, w1, b1, nullptr, hbuf, D_FF, D_MODEL);
    // FFN2: out = x1 + h @ w2^T + b2
    gemm_nt<1><<<g1024, 256>>>(hbuf, w2, b2, x1, out, D_MODEL, D_FF);
}

// round 2
// speedup vs baseline: 2.5424x; 2.5424x over previous
#include <cuda_runtime.h>
#include <math.h>
#include <stdint.h>

#define BATCH 4
#define SEQ 2048
#define M_ROWS 8192          // BATCH*SEQ
#define D_MODEL 1024
#define NH 16
#define DK 64
#define D_FF 4096

// ---------------- scratch (device globals; no allocation allowed) ----------------
__device__ float g_xn[M_ROWS * D_MODEL];    // layernorm output
__device__ float g_q[M_ROWS * D_MODEL];     // (b,h,s,d)
__device__ float g_k[M_ROWS * D_MODEL];     // (b,h,s,d)
__device__ float g_v[M_ROWS * D_MODEL];     // (b,h,s,d)
__device__ float g_attn[M_ROWS * D_MODEL];  // (b,s,h*dk) row-major
__device__ float g_x1[M_ROWS * D_MODEL];    // residual after attention
__device__ float g_h[M_ROWS * D_FF];        // FFN hidden

// ---------------- tf32 helpers ----------------
__device__ __forceinline__ uint32_t f2tf32(float f) {
    uint32_t u;
    asm("cvt.rna.tf32.f32 %0, %1;" : "=r"(u) : "f"(f));
    return u;
}

__device__ __forceinline__ void mma_tf32(float* c, const uint32_t* a, const uint32_t* b) {
    asm volatile(
        "mma.sync.aligned.m16n8k8.row.col.f32.tf32.tf32.f32 "
        "{%0,%1,%2,%3}, {%4,%5,%6,%7}, {%8,%9}, {%0,%1,%2,%3};"
        : "+f"(c[0]), "+f"(c[1]), "+f"(c[2]), "+f"(c[3])
        : "r"(a[0]), "r"(a[1]), "r"(a[2]), "r"(a[3]), "r"(b[0]), "r"(b[1]));
}

// ---------------- block reduction helper ----------------
__device__ __forceinline__ float block_sum_256(float v, float* red) {
    int t = threadIdx.x;
    #pragma unroll
    for (int o = 16; o; o >>= 1) v += __shfl_xor_sync(0xffffffffu, v, o);
    if ((t & 31) == 0) red[t >> 5] = v;
    __syncthreads();
    if (t < 32) {
        float r = (t < 8) ? red[t] : 0.f;
        #pragma unroll
        for (int o = 4; o; o >>= 1) r += __shfl_xor_sync(0xffffffffu, r, o);
        if (t == 0) red[0] = r;
    }
    __syncthreads();
    float out = red[0];
    __syncthreads();
    return out;
}

// ---------------- LayerNorm: one block per row, 256 threads ----------------
__global__ void ln_kernel(const float* __restrict__ x, const float* __restrict__ gamma,
                          const float* __restrict__ beta, float* __restrict__ out) {
    __shared__ float red[8];
    int row = blockIdx.x;
    int t = threadIdx.x;
    const float4* xr = (const float4*)(x + (size_t)row * D_MODEL);
    float4 v = xr[t];
    float mean = block_sum_256(v.x + v.y + v.z + v.w, red) * (1.0f / D_MODEL);
    float dx = v.x - mean, dy = v.y - mean, dz = v.z - mean, dw = v.w - mean;
    float var = block_sum_256(dx * dx + dy * dy + dz * dz + dw * dw, red) * (1.0f / D_MODEL);
    float rstd = rsqrtf(var + 1e-6f);
    float4 ga = ((const float4*)gamma)[t];
    float4 bb = ((const float4*)beta)[t];
    float4 o;
    o.x = ga.x * dx * rstd + bb.x;
    o.y = ga.y * dy * rstd + bb.y;
    o.z = ga.z * dz * rstd + bb.z;
    o.w = ga.w * dw * rstd + bb.w;
    ((float4*)(out + (size_t)row * D_MODEL))[t] = o;
}

// ---------------- tf32 tensor-core GEMM: C[M,N] = A[M,K] * W[N,K]^T ----------------
// 128x128 block tile, BK=32, 256 threads = 8 warps (2 x 4), warp tile 64x32,
// per warp 4x4 m16n8k8 tiles. Smem stride 36 -> fragment loads conflict-free.
// MODE 0: scatter to (b,h,s,d) layout.  MODE 1: C = res + A*W^T (+bias).
// MODE 2: C = relu(A*W^T + bias)
template <int MODE>
__global__ __launch_bounds__(256) void gemm_tf32(
    const float* __restrict__ A, const float* __restrict__ W,
    const float* __restrict__ bias, const float* __restrict__ res,
    float* __restrict__ C, int N, int K) {
    __shared__ uint32_t As[128][36];
    __shared__ uint32_t Bs[128][36];
    int tid = threadIdx.x, lane = tid & 31, warp = tid >> 5;
    int wm = warp >> 2, wn = warp & 3;      // 2 x 4 warp grid
    int gid = lane >> 2, tig = lane & 3;
    int bm = blockIdx.y * 128, bn = blockIdx.x * 128;
    float acc[4][4][4] = {};
    const float* Ab = A + (size_t)bm * K;
    const float* Wb = W + (size_t)bn * K;
    int lr = tid >> 3;           // 0..31
    int lc = (tid & 7) * 4;      // 0..28
    for (int k0 = 0; k0 < K; k0 += 32) {
        #pragma unroll
        for (int it = 0; it < 4; it++) {
            int r = lr + it * 32;
            float4 av = *(const float4*)(Ab + (size_t)r * K + k0 + lc);
            As[r][lc + 0] = f2tf32(av.x); As[r][lc + 1] = f2tf32(av.y);
            As[r][lc + 2] = f2tf32(av.z); As[r][lc + 3] = f2tf32(av.w);
            float4 wv = *(const float4*)(Wb + (size_t)r * K + k0 + lc);
            Bs[r][lc + 0] = f2tf32(wv.x); Bs[r][lc + 1] = f2tf32(wv.y);
            Bs[r][lc + 2] = f2tf32(wv.z); Bs[r][lc + 3] = f2tf32(wv.w);
        }
        __syncthreads();
        #pragma unroll
        for (int kk = 0; kk < 32; kk += 8) {
            uint32_t af[4][4], bf[4][2];
            #pragma unroll
            for (int mt = 0; mt < 4; mt++) {
                int rrow = wm * 64 + mt * 16 + gid;
                af[mt][0] = As[rrow][kk + tig];
                af[mt][1] = As[rrow + 8][kk + tig];
                af[mt][2] = As[rrow][kk + tig + 4];
                af[mt][3] = As[rrow + 8][kk + tig + 4];
            }
            #pragma unroll
            for (int nt = 0; nt < 4; nt++) {
                int col = wn * 32 + nt * 8 + gid;
                bf[nt][0] = Bs[col][kk + tig];
                bf[nt][1] = Bs[col][kk + tig + 4];
            }
            #pragma unroll
            for (int mt = 0; mt < 4; mt++)
                #pragma unroll
                for (int nt = 0; nt < 4; nt++)
                    mma_tf32(acc[mt][nt], af[mt], bf[nt]);
        }
        __syncthreads();
    }
    // epilogue: fragment (mt,nt,r): row = wm*64+mt*16+gid+(r>=2?8:0), col = wn*32+nt*8+2*tig+(r&1)
    #pragma unroll
    for (int mt = 0; mt < 4; mt++) {
        #pragma unroll
        for (int nt = 0; nt < 4; nt++) {
            #pragma unroll
            for (int r = 0; r < 4; r++) {
                int m = bm + wm * 64 + mt * 16 + gid + ((r >> 1) << 3);
                int n = bn + wn * 32 + nt * 8 + 2 * tig + (r & 1);
                float c = acc[mt][nt][r];
                if (MODE == 0) {
                    int b = m >> 11, s = m & 2047, h = n >> 6, d = n & 63;
                    C[(((size_t)(b * NH + h) * SEQ + s) << 6) + d] = c;
                } else if (MODE == 1) {
                    if (bias) c += bias[n];
                    C[(size_t)m * N + n] = res[(size_t)m * N + n] + c;
                } else {
                    c += bias[n];
                    C[(size_t)m * N + n] = fmaxf(c, 0.0f);
                }
            }
        }
    }
}

// ---------------- Flash attention, tf32 tensor cores, 64q x 64k tiles --------------
// grid: (B*H, SEQ/64), 256 threads = 8 warps (4m x 2n), warp tile 16x32 of the
// 64x64 score/output tile. Q fragments preloaded from gmem; K, V^T, P in smem.
__global__ __launch_bounds__(256) void attn_kernel(
    const float* __restrict__ q, const float* __restrict__ k,
    const float* __restrict__ v, const int* __restrict__ mask,
    float* __restrict__ out) {
    extern __shared__ char smraw[];
    uint32_t* Ks = (uint32_t*)smraw;                 // [64][68] tf32 (key, d)
    uint32_t* Vs = Ks + 64 * 68;                     // [64][68] tf32 (d, key)  TRANSPOSED
    float*    Psf = (float*)(Vs + 64 * 68);          // [64][68] scores, then P (tf32 bits)
    uint32_t* Psu = (uint32_t*)Psf;
    float* row_m = Psf + 64 * 68;
    float* row_l = row_m + 64;
    float* row_sc = row_l + 64;
    int*   Msk = (int*)(row_sc + 64);

    int bh = blockIdx.x;    // b*NH + h
    int qt = blockIdx.y;
    int b = bh >> 4;
    int h = bh & 15;
    int tid = threadIdx.x, lane = tid & 31, warp = tid >> 5;
    int wm = warp >> 1, wn = warp & 1;     // 4 x 2 warp grid
    int gid = lane >> 2, tig = lane & 3;

    const float* kbase = k + (size_t)bh * SEQ * DK;
    const float* vbase = v + (size_t)bh * SEQ * DK;
    const int* mbase = mask + b * SEQ;

    // preload Q fragments straight from gmem (rows wm*16 + gid / +8)
    const float* qbase = q + ((size_t)bh * SEQ + qt * 64 + wm * 16) * DK;
    uint32_t qf[8][4];
    #pragma unroll
    for (int kk = 0; kk < 8; kk++) {
        qf[kk][0] = f2tf32(qbase[(size_t)gid * DK + kk * 8 + tig]);
        qf[kk][1] = f2tf32(qbase[(size_t)(gid + 8) * DK + kk * 8 + tig]);
        qf[kk][2] = f2tf32(qbase[(size_t)gid * DK + kk * 8 + tig + 4]);
        qf[kk][3] = f2tf32(qbase[(size_t)(gid + 8) * DK + kk * 8 + tig + 4]);
    }

    if (tid < 64) { row_m[tid] = -1e30f; row_l[tid] = 0.f; }

    float oacc[4][4] = {};      // O accumulator: 4 n-tiles x 4 regs (16x32 strip)
    const float scale = 0.125f; // 1/sqrt(64)

    for (int kt = 0; kt < SEQ; kt += 64) {
        // load K (direct) and V (transposed) tiles as tf32, mask slice
        #pragma unroll
        for (int it = 0; it < 4; it++) {
            int i = tid + it * 256;
            int r = i >> 4, c = (i & 15) * 4;
            float4 t4 = *(const float4*)(kbase + (size_t)(kt + r) * DK + c);
            Ks[r * 68 + c + 0] = f2tf32(t4.x); Ks[r * 68 + c + 1] = f2tf32(t4.y);
            Ks[r * 68 + c + 2] = f2tf32(t4.z); Ks[r * 68 + c + 3] = f2tf32(t4.w);
            float4 u4 = *(const float4*)(vbase + (size_t)(kt + r) * DK + c);
            Vs[(c + 0) * 68 + r] = f2tf32(u4.x); Vs[(c + 1) * 68 + r] = f2tf32(u4.y);
            Vs[(c + 2) * 68 + r] = f2tf32(u4.z); Vs[(c + 3) * 68 + r] = f2tf32(u4.w);
        }
        if (tid < 64) Msk[tid] = mbase[kt + tid];
        __syncthreads();

        // S = Q K^T  (warp strip: rows wm*16..+16, cols wn*32..+32)
        float sacc[4][4] = {};
        #pragma unroll
        for (int kk = 0; kk < 8; kk++) {
            uint32_t bf[4][2];
            #pragma unroll
            for (int nt = 0; nt < 4; nt++) {
                int col = wn * 32 + nt * 8 + gid;
                bf[nt][0] = Ks[col * 68 + kk * 8 + tig];
                bf[nt][1] = Ks[col * 68 + kk * 8 + tig + 4];
            }
            #pragma unroll
            for (int nt = 0; nt < 4; nt++)
                mma_tf32(sacc[nt], qf[kk], bf[nt]);
        }
        // scale + mask, write scores to smem
        #pragma unroll
        for (int nt = 0; nt < 4; nt++) {
            #pragma unroll
            for (int r = 0; r < 4; r++) {
                int row = wm * 16 + gid + ((r >> 1) << 3);
                int col = wn * 32 + nt * 8 + 2 * tig + (r & 1);
                float sv = sacc[nt][r] * scale;
                if (Msk[col] == 0) sv = -1e30f;
                Psf[row * 68 + col] = sv;
            }
        }
        __syncthreads();

        // online softmax: 4 threads per row, 16 cols each
        {
            int row = tid >> 2;
            int c0 = (tid & 3) * 16;
            float sv[16], tmax = -1e30f;
            #pragma unroll
            for (int j = 0; j < 16; j++) {
                sv[j] = Psf[row * 68 + c0 + j];
                tmax = fmaxf(tmax, sv[j]);
            }
            tmax = fmaxf(tmax, __shfl_xor_sync(0xffffffffu, tmax, 1));
            tmax = fmaxf(tmax, __shfl_xor_sync(0xffffffffu, tmax, 2));
            float m_old = row_m[row];
            float m_new = fmaxf(m_old, tmax);
            float lsum = 0.f;
            #pragma unroll
            for (int j = 0; j < 16; j++) {
                float p = __expf(sv[j] - m_new);
                lsum += p;
                Psu[row * 68 + c0 + j] = f2tf32(p);
            }
            lsum += __shfl_xor_sync(0xffffffffu, lsum, 1);
            lsum += __shfl_xor_sync(0xffffffffu, lsum, 2);
            if ((tid & 3) == 0) {
                float sc = __expf(m_old - m_new);
                row_l[row] = row_l[row] * sc + lsum;
                row_m[row] = m_new;
                row_sc[row] = sc;
            }
        }
        __syncthreads();

        // rescale O accumulator
        {
            float s0 = row_sc[wm * 16 + gid];
            float s1 = row_sc[wm * 16 + gid + 8];
            #pragma unroll
            for (int nt = 0; nt < 4; nt++) {
                oacc[nt][0] *= s0; oacc[nt][1] *= s0;
                oacc[nt][2] *= s1; oacc[nt][3] *= s1;
            }
        }

        // O += P V   (A = P rows wm*16.., B = V^T: Vs[d][key])
        #pragma unroll
        for (int kk = 0; kk < 8; kk++) {
            uint32_t af[4], bf[4][2];
            int rbase = (wm * 16 + gid) * 68;
            af[0] = Psu[rbase + kk * 8 + tig];
            af[1] = Psu[rbase + 8 * 68 + kk * 8 + tig];
            af[2] = Psu[rbase + kk * 8 + tig + 4];
            af[3] = Psu[rbase + 8 * 68 + kk * 8 + tig + 4];
            #pragma unroll
            for (int nt = 0; nt < 4; nt++) {
                int col = wn * 32 + nt * 8 + gid;
                bf[nt][0] = Vs[col * 68 + kk * 8 + tig];
                bf[nt][1] = Vs[col * 68 + kk * 8 + tig + 4];
            }
            #pragma unroll
            for (int nt = 0; nt < 4; nt++)
                mma_tf32(oacc[nt], af, bf[nt]);
        }
        __syncthreads();
    }

    // finalize: divide by l, write (b, s, h*DK + d)
    float inv0 = 1.0f / row_l[wm * 16 + gid];
    float inv1 = 1.0f / row_l[wm * 16 + gid + 8];
    #pragma unroll
    for (int nt = 0; nt < 4; nt++) {
        #pragma unroll
        for (int r = 0; r < 4; r++) {
            int row = wm * 16 + gid + ((r >> 1) << 3);
            int col = wn * 32 + nt * 8 + 2 * tig + (r & 1);
            int srow = qt * 64 + row;
            out[((size_t)b * SEQ + srow) * D_MODEL + h * DK + col] =
                oacc[nt][r] * ((r >> 1) ? inv1 : inv0);
        }
    }
}

// ---------------- launch ----------------
extern "C" void kernel_launch(void* const* d_in, const int* in_sizes, int n_in,
                              void* d_out, int out_size) {
    const float* x      = (const float*)d_in[0];
    const int*   mask   = (const int*)d_in[1];
    const float* wq     = (const float*)d_in[2];
    const float* wk     = (const float*)d_in[3];
    const float* wv     = (const float*)d_in[4];
    const float* wo     = (const float*)d_in[5];
    const float* ln1_a  = (const float*)d_in[6];
    const float* ln1_b  = (const float*)d_in[7];
    const float* ln2_a  = (const float*)d_in[8];
    const float* ln2_b  = (const float*)d_in[9];
    const float* w1     = (const float*)d_in[10];
    const float* b1     = (const float*)d_in[11];
    const float* w2     = (const float*)d_in[12];
    const float* b2     = (const float*)d_in[13];
    float* out = (float*)d_out;

    float *xn, *q, *k, *v, *attn, *x1, *hbuf;
    cudaGetSymbolAddress((void**)&xn, g_xn);
    cudaGetSymbolAddress((void**)&q, g_q);
    cudaGetSymbolAddress((void**)&k, g_k);
    cudaGetSymbolAddress((void**)&v, g_v);
    cudaGetSymbolAddress((void**)&attn, g_attn);
    cudaGetSymbolAddress((void**)&x1, g_x1);
    cudaGetSymbolAddress((void**)&hbuf, g_h);

    // LN1
    ln_kernel<<<M_ROWS, 256>>>(x, ln1_a, ln1_b, xn);
    // QKV projections (scatter to b,h,s,d)
    dim3 g1024(D_MODEL / 128, M_ROWS / 128);
    gemm_tf32<0><<<g1024, 256>>>(xn, wq, nullptr, nullptr, q, D_MODEL, D_MODEL);
    gemm_tf32<0><<<g1024, 256>>>(xn, wk, nullptr, nullptr, k, D_MODEL, D_MODEL);
    gemm_tf32<0><<<g1024, 256>>>(xn, wv, nullptr, nullptr, v, D_MODEL, D_MODEL);
    // attention
    size_t smem = (size_t)(64 * 68 * 3 + 3 * 64 + 64) * 4;
    cudaFuncSetAttribute(attn_kernel, cudaFuncAttributeMaxDynamicSharedMemorySize, (int)smem);
    attn_kernel<<<dim3(BATCH * NH, SEQ / 64), 256, smem>>>(q, k, v, mask, attn);
    // O-projection + residual: x1 = x + attn @ wo^T
    gemm_tf32<1><<<g1024, 256>>>(attn, wo, nullptr, x, x1, D_MODEL, D_MODEL);
    // LN2
    ln_kernel<<<M_ROWS, 256>>>(x1, ln2_a, ln2_b, xn);
    // FFN1: h = relu(xn @ w1^T + b1)
    dim3 gff(D_FF / 128, M_ROWS / 128);
    gemm_tf32<2><<<gff, 256>>>(xn, w1, b1, nullptr, hbuf, D_FF, D_MODEL);
    // FFN2: out = x1 + h @ w2^T + b2
    gemm_tf32<1><<<g1024, 256>>>(hbuf, w2, b2, x1, out, D_MODEL, D_FF);
}